// round 15
// baseline (speedup 1.0000x reference)
#include <cuda_runtime.h>

#define BB 16
#define SS 2048
#define NC 8
#define NT 512
#define NW (NT / 32)           // 16 warps
#define CHUNK 4                // SS / NT
#define LOG2E 1.4426950408889634f
#define T1V 100.0f
#define EPSV 1e-8f

__device__ __forceinline__ float ex2(float x) {
    float y; asm("ex2.approx.ftz.f32 %0, %1;" : "=f"(y) : "f"(x)); return y;
}
__device__ __forceinline__ float flog(float x) {
    float y; asm("lg2.approx.ftz.f32 %0, %1;" : "=f"(y) : "f"(x));
    return y * 0.6931471805599453f;
}

// Cross-block state (no allocations). Replay-safe.
__device__ double   g_partials[BB];
__device__ unsigned g_ticket;          // winner resets to 0 each run

__global__ __launch_bounds__(NT)
void hawkes_kernel(const float* __restrict__ ts,
                   const int*   __restrict__ ms,
                   const float* __restrict__ mu,
                   const float* __restrict__ alphas,
                   const float* __restrict__ beta,
                   float*       __restrict__ out)
{
    __shared__ alignas(16) float AB[NC * NC];  // alphas[m][c] * beta[c], row-aligned for LDS.128
    __shared__ float  colsum[NC];        // sum_k alphas[k][c]
    __shared__ float  mu_s[NC];
    __shared__ float  Wagg[NW][NC + 1];  // per-warp channel sums (anchored at own Tw)
    __shared__ float  WT[NW];            // per-warp anchor timestamps
    __shared__ float  Ew[NW][NC + 1];    // PRE-DECAYED exclusive base, anchored at WT[w]
    __shared__ float  wsum[NW];          // per-warp float partials

    const int b    = blockIdx.x;         // one block per batch row
    const int t    = threadIdx.x;
    const int w    = t >> 5;
    const int lane = t & 31;

    // ---- Per-thread params (const cache; no barrier needed) ----
    float bl2[NC];
    #pragma unroll
    for (int c = 0; c < NC; c++) bl2[c] = __ldg(&beta[c]) * LOG2E;

    // ---- Stage small params into smem (covered by the scan barrier below) ----
    if (t < NC * NC) AB[t] = alphas[t] * __ldg(&beta[t & (NC - 1)]);
    if (t < NC) {
        float s = 0.f;
        #pragma unroll
        for (int k = 0; k < NC; k++) s += alphas[k * NC + t];
        colsum[t] = s;
        mu_s[t]   = mu[t];
    }

    // ---- Load this thread's 4 events (LDG.128, coalesced) ----
    float tloc[CHUNK];
    int   mloc[CHUNK];
    *(float4*)tloc = ((const float4*)(ts + b * SS))[t];
    *(int4*)mloc   = ((const int4*)  (ms + b * SS))[t];

    // Warp anchor = last event time in warp (sorted ascending)
    const float Tw = __shfl_sync(0xffffffffu, tloc[CHUNK - 1], 31);

    // ---- Anchored event weights (independent ex2s) ----
    float ev[CHUNK];
    #pragma unroll
    for (int j = 0; j < CHUNK; j++)
        ev[j] = (tloc[j] > 0.f) ? ex2(bl2[mloc[j]] * (tloc[j] - Tw)) : 0.f;

    // ---- Chunk channel sums (kept in P for exclusive-by-subtraction) ----
    float P[NC];
    #pragma unroll
    for (int c = 0; c < NC; c++) P[c] = 0.f;
    #pragma unroll
    for (int j = 0; j < CHUNK; j++) P[mloc[j]] += ev[j];

    // ---- Warp inclusive Kogge-Stone: PLAIN ADDS (common anchor) ----
    float V[NC];
    #pragma unroll
    for (int c = 0; c < NC; c++) V[c] = P[c];
    #pragma unroll
    for (int off = 1; off < 32; off <<= 1) {
        float Vp[NC];
        #pragma unroll
        for (int c = 0; c < NC; c++) Vp[c] = __shfl_up_sync(0xffffffffu, V[c], off);
        if (lane >= off) {
            #pragma unroll
            for (int c = 0; c < NC; c++) V[c] += Vp[c];
        }
    }
    if (lane == 31) {
        #pragma unroll
        for (int c = 0; c < NC; c++) Wagg[w][c] = V[c];
        WT[w] = Tw;
    }
    __syncthreads();

    // ---- t<8: serial cross-warp scan; publish PRE-DECAYED exclusive bases ----
    // dec[ww] = decay from WT[ww-1] to WT[ww]; all independent ex2s, chain is FMA-only.
    if (t < NC) {
        const int c = t;
        float dec[NW];
        #pragma unroll
        for (int ww = 1; ww < NW; ww++)
            dec[ww] = ex2(bl2[c] * (WT[ww - 1] - WT[ww]));
        Ew[0][c] = 0.f;
        float run = Wagg[0][c];                  // inclusive through warp 0
        #pragma unroll
        for (int ww = 1; ww < NW; ww++) {
            float base = run * dec[ww];          // exclusive base anchored at WT[ww]
            Ew[ww][c] = base;
            run = base + Wagg[ww][c];            // inclusive through warp ww
        }
    }
    __syncthreads();

    // ---- Exclusive prefix state S anchored at Tw: (V - P) + Ew[w] ----
    // V - P = contribution of preceding lanes in this warp (exact; lane 0 -> 0).
    float S[NC];
    #pragma unroll
    for (int c = 0; c < NC; c++)
        S[c] = (V[c] - P[c]) + Ew[w][c];

    // ---- Per-event log-likelihood terms (independent; float accumulation) ----
    float acc = 0.f;
    #pragma unroll
    for (int j = 0; j < CHUNK; j++) {
        const float ti = tloc[j];
        const int   m  = mloc[j];
        if (ti > 0.f) {
            // AB row of class m via two LDS.128
            const float4 a0 = ((const float4*)AB)[m * 2];
            const float4 a1 = ((const float4*)AB)[m * 2 + 1];
            const float dT = Tw - ti;            // >= 0, warp-bounded
            float lam = mu_s[m];
            lam += a0.x * S[0] * ex2(bl2[0] * dT);
            lam += a0.y * S[1] * ex2(bl2[1] * dT);
            lam += a0.z * S[2] * ex2(bl2[2] * dT);
            lam += a0.w * S[3] * ex2(bl2[3] * dT);
            lam += a1.x * S[4] * ex2(bl2[4] * dT);
            lam += a1.y * S[5] * ex2(bl2[5] * dT);
            lam += a1.z * S[6] * ex2(bl2[6] * dT);
            lam += a1.w * S[7] * ex2(bl2[7] * dT);
            acc += flog(lam + EPSV)
                 - colsum[m] * (1.f - ex2(-bl2[m] * (T1V - ti)));
        }
        S[m] += ev[j];   // event j becomes source for later events in chunk
    }

    // ---- Warp reduce (float), publish per-warp partials ----
    #pragma unroll
    for (int off = 16; off > 0; off >>= 1)
        acc += __shfl_down_sync(0xffffffffu, acc, off);
    if (lane == 0) wsum[w] = acc;
    __syncthreads();

    // ---- Warp 0: block partial + ticketed PARALLEL finalize ----
    if (w == 0) {
        float v = (lane < NW) ? wsum[lane] : 0.f;
        #pragma unroll
        for (int off = 8; off > 0; off >>= 1)
            v += __shfl_down_sync(0xffffffffu, v, off);     // lanes 16+ are 0

        unsigned tk = 0;
        if (lane == 0) {
            g_partials[b] = (double)v;
            __threadfence();
            tk = atomicAdd(&g_ticket, 1u);
        }
        tk = __shfl_sync(0xffffffffu, tk, 0);

        if (tk == BB - 1) {                 // last block: one lane per row partial
            __threadfence();
            double dv = (lane < BB) ? (double)__ldcg(&g_partials[lane]) : 0.0;
            #pragma unroll
            for (int off = 8; off > 0; off >>= 1)
                dv += __shfl_down_sync(0xffffffffu, dv, off);   // deterministic tree
            if (lane == 0) {
                double musum = 0.0;
                #pragma unroll
                for (int c = 0; c < NC; c++) musum += (double)mu_s[c];
                out[0] = (float)(dv - musum * (double)T1V);
                __threadfence();
                g_ticket = 0;               // reset for next graph replay
            }
        }
    }
}

extern "C" void kernel_launch(void* const* d_in, const int* in_sizes, int n_in,
                              void* d_out, int out_size)
{
    const float* ts     = (const float*)d_in[0];
    const int*   ms     = (const int*)  d_in[1];
    const float* mu     = (const float*)d_in[2];
    const float* alphas = (const float*)d_in[3];
    const float* beta   = (const float*)d_in[4];
    float*       out    = (float*)d_out;

    hawkes_kernel<<<BB, NT>>>(ts, ms, mu, alphas, beta, out);
}

// round 16
// speedup vs baseline: 1.0278x; 1.0278x over previous
#include <cuda_runtime.h>

#define BB 16
#define SS 2048
#define NC 8
#define NT 512
#define NW (NT / 32)           // 16 warps
#define CHUNK 4                // SS / NT
#define LOG2E 1.4426950408889634f
#define LN2   0.6931471805599453f
#define T1V 100.0f
#define EPSV 1e-8f

__device__ __forceinline__ float ex2(float x) {
    float y; asm("ex2.approx.ftz.f32 %0, %1;" : "=f"(y) : "f"(x)); return y;
}
__device__ __forceinline__ float lg2(float x) {
    float y; asm("lg2.approx.ftz.f32 %0, %1;" : "=f"(y) : "f"(x)); return y;
}

// Cross-block state (no allocations). Replay-safe.
__device__ double   g_partials[BB];
__device__ unsigned g_ticket;          // winner resets to 0 each run

__global__ __launch_bounds__(NT)
void hawkes_kernel(const float* __restrict__ ts,
                   const int*   __restrict__ ms,
                   const float* __restrict__ mu,
                   const float* __restrict__ alphas,
                   const float* __restrict__ beta,
                   float*       __restrict__ out)
{
    __shared__ alignas(16) float AB[NC * NC];   // alphas[m][c] * beta[c]
    __shared__ alignas(16) float bl2_sh[NC];    // beta[c] * log2(e)
    __shared__ float  colsum[NC];        // sum_k alphas[k][c]
    __shared__ float  mu_s[NC];
    __shared__ float  Wagg[NW][NC + 1];  // per-warp channel sums (anchored at own Tw)
    __shared__ float  WT[NW];            // per-warp anchor timestamps
    __shared__ float  Ew[NW][NC + 1];    // PRE-DECAYED exclusive base, anchored at WT[w]
    __shared__ float  wsum[NW];          // per-warp float partials

    const int b    = blockIdx.x;         // one block per batch row
    const int t    = threadIdx.x;
    const int w    = t >> 5;
    const int lane = t & 31;

    // ---- Issue event loads FIRST (hide behind param staging + barrier) ----
    float tloc[CHUNK];
    int   mloc[CHUNK];
    *(float4*)tloc = ((const float4*)(ts + b * SS))[t];
    *(int4*)mloc   = ((const int4*)  (ms + b * SS))[t];

    // ---- Stage params once (few threads), then one barrier ----
    if (t < NC * NC) AB[t] = alphas[t] * __ldg(&beta[t & (NC - 1)]);
    if (t < NC) {
        float s = 0.f;
        #pragma unroll
        for (int k = 0; k < NC; k++) s += alphas[k * NC + t];
        colsum[t]  = s;
        mu_s[t]    = mu[t];
        bl2_sh[t]  = __ldg(&beta[t]) * LOG2E;
    }
    __syncthreads();

    // bl2 into registers via two LDS.128 (broadcast, conflict-free)
    float bl2[NC];
    {
        const float4 b0 = ((const float4*)bl2_sh)[0];
        const float4 b1 = ((const float4*)bl2_sh)[1];
        bl2[0] = b0.x; bl2[1] = b0.y; bl2[2] = b0.z; bl2[3] = b0.w;
        bl2[4] = b1.x; bl2[5] = b1.y; bl2[6] = b1.z; bl2[7] = b1.w;
    }

    // Warp anchor = last event time in warp (sorted ascending)
    const float Tw = __shfl_sync(0xffffffffu, tloc[CHUNK - 1], 31);

    // ---- Anchored event weights (independent ex2s) ----
    float ev[CHUNK];
    #pragma unroll
    for (int j = 0; j < CHUNK; j++)
        ev[j] = (tloc[j] > 0.f) ? ex2(bl2[mloc[j]] * (tloc[j] - Tw)) : 0.f;

    // ---- Chunk channel sums (kept in P for exclusive-by-subtraction) ----
    float P[NC];
    #pragma unroll
    for (int c = 0; c < NC; c++) P[c] = 0.f;
    #pragma unroll
    for (int j = 0; j < CHUNK; j++) P[mloc[j]] += ev[j];

    // ---- Warp inclusive Kogge-Stone: PLAIN ADDS (common anchor) ----
    float V[NC];
    #pragma unroll
    for (int c = 0; c < NC; c++) V[c] = P[c];
    #pragma unroll
    for (int off = 1; off < 32; off <<= 1) {
        float Vp[NC];
        #pragma unroll
        for (int c = 0; c < NC; c++) Vp[c] = __shfl_up_sync(0xffffffffu, V[c], off);
        if (lane >= off) {
            #pragma unroll
            for (int c = 0; c < NC; c++) V[c] += Vp[c];
        }
    }
    if (lane == 31) {
        #pragma unroll
        for (int c = 0; c < NC; c++) Wagg[w][c] = V[c];
        WT[w] = Tw;
    }
    __syncthreads();

    // ---- t<8: serial cross-warp scan; publish PRE-DECAYED exclusive bases ----
    if (t < NC) {
        const int c = t;
        float dec[NW];
        #pragma unroll
        for (int ww = 1; ww < NW; ww++)
            dec[ww] = ex2(bl2[c] * (WT[ww - 1] - WT[ww]));   // independent ex2s
        Ew[0][c] = 0.f;
        float run = Wagg[0][c];
        #pragma unroll
        for (int ww = 1; ww < NW; ww++) {
            float base = run * dec[ww];          // exclusive base anchored at WT[ww]
            Ew[ww][c] = base;
            run = base + Wagg[ww][c];
        }
    }
    __syncthreads();

    // ---- Exclusive prefix state S anchored at Tw: (V - P) + Ew[w] ----
    float S[NC];
    #pragma unroll
    for (int c = 0; c < NC; c++)
        S[c] = (V[c] - P[c]) + Ew[w][c];

    // ---- Per-event terms: accumulate lg2(lam) and compensator separately ----
    float accL = 0.f;   // sum of lg2(lam)
    float accC = 0.f;   // sum of colsum[m]*(1 - ex2(...))
    #pragma unroll
    for (int j = 0; j < CHUNK; j++) {
        const float ti = tloc[j];
        const int   m  = mloc[j];
        if (ti > 0.f) {
            const float4 a0 = ((const float4*)AB)[m * 2];
            const float4 a1 = ((const float4*)AB)[m * 2 + 1];
            const float dT = Tw - ti;            // >= 0, warp-bounded
            float lam = mu_s[m];
            lam += a0.x * S[0] * ex2(bl2[0] * dT);
            lam += a0.y * S[1] * ex2(bl2[1] * dT);
            lam += a0.z * S[2] * ex2(bl2[2] * dT);
            lam += a0.w * S[3] * ex2(bl2[3] * dT);
            lam += a1.x * S[4] * ex2(bl2[4] * dT);
            lam += a1.y * S[5] * ex2(bl2[5] * dT);
            lam += a1.z * S[6] * ex2(bl2[6] * dT);
            lam += a1.w * S[7] * ex2(bl2[7] * dT);
            accL += lg2(lam + EPSV);
            accC += colsum[m] * (1.f - ex2(-bl2[m] * (T1V - ti)));
        }
        S[m] += ev[j];   // event j becomes source for later events in chunk
    }
    float acc = fmaf(accL, LN2, -accC);

    // ---- Warp reduce (float), publish per-warp partials ----
    #pragma unroll
    for (int off = 16; off > 0; off >>= 1)
        acc += __shfl_down_sync(0xffffffffu, acc, off);
    if (lane == 0) wsum[w] = acc;
    __syncthreads();

    // ---- Warp 0: block partial + ticketed PARALLEL finalize ----
    if (w == 0) {
        float v = (lane < NW) ? wsum[lane] : 0.f;
        #pragma unroll
        for (int off = 8; off > 0; off >>= 1)
            v += __shfl_down_sync(0xffffffffu, v, off);     // lanes 16+ are 0

        unsigned tk = 0;
        if (lane == 0) {
            g_partials[b] = (double)v;
            __threadfence();
            tk = atomicAdd(&g_ticket, 1u);
        }
        tk = __shfl_sync(0xffffffffu, tk, 0);

        if (tk == BB - 1) {                 // last block: one lane per row partial
            __threadfence();
            double dv = (lane < BB) ? (double)__ldcg(&g_partials[lane]) : 0.0;
            #pragma unroll
            for (int off = 8; off > 0; off >>= 1)
                dv += __shfl_down_sync(0xffffffffu, dv, off);   // deterministic tree
            if (lane == 0) {
                double musum = 0.0;
                #pragma unroll
                for (int c = 0; c < NC; c++) musum += (double)mu_s[c];
                out[0] = (float)(dv - musum * (double)T1V);
                __threadfence();
                g_ticket = 0;               // reset for next graph replay
            }
        }
    }
}

extern "C" void kernel_launch(void* const* d_in, const int* in_sizes, int n_in,
                              void* d_out, int out_size)
{
    const float* ts     = (const float*)d_in[0];
    const int*   ms     = (const int*)  d_in[1];
    const float* mu     = (const float*)d_in[2];
    const float* alphas = (const float*)d_in[3];
    const float* beta   = (const float*)d_in[4];
    float*       out    = (float*)d_out;

    hawkes_kernel<<<BB, NT>>>(ts, ms, mu, alphas, beta, out);
}